// round 1
// baseline (speedup 1.0000x reference)
#include <cuda_runtime.h>
#include <math.h>

#define MAXN 50000
#define MAXE 800000

__device__ float g_q[MAXN * 128];
__device__ float g_k[MAXN * 128];
__device__ float g_v[MAXN * 128];
__device__ float g_wk[(size_t)MAXN * 256];   // [n][d(64)][h(4)]
__device__ float g_bk[MAXN * 4];
__device__ float g_scores[(size_t)MAXE * 4]; // [e][h], reused for exp values
__device__ int   g_rowptr[MAXN + 1];
__device__ float g_att[MAXN * 128];

// ---------------------------------------------------------------------------
// Tiled SGEMM: C[Nrows,M] = A[Nrows,K] @ W[K,M] + bias  (fp32)
// BM=64 BN=64 BK=16, 256 threads, 4x4 microtile
// ---------------------------------------------------------------------------
__global__ void sgemm_bias_kernel(const float* __restrict__ A,
                                  const float* __restrict__ W,
                                  const float* __restrict__ bias,
                                  float* __restrict__ C,
                                  int Nrows, int K, int M) {
    __shared__ float As[16][64];
    __shared__ float Bs[16][64];
    int t = threadIdx.x;
    int tx = t & 15, ty = t >> 4;
    int rowBase = blockIdx.y * 64;
    int colBase = blockIdx.x * 64;

    float acc[4][4] = {};

    int aRow = t >> 2;           // 0..63
    int aCol = (t & 3) << 2;     // 0,4,8,12
    int bRow = t >> 4;           // 0..15
    int bCol = (t & 15) << 2;    // 0..60

    for (int k0 = 0; k0 < K; k0 += 16) {
        float4 av = make_float4(0.f, 0.f, 0.f, 0.f);
        int gr = rowBase + aRow;
        if (gr < Nrows)
            av = *(const float4*)(A + (size_t)gr * K + k0 + aCol);
        As[aCol + 0][aRow] = av.x;
        As[aCol + 1][aRow] = av.y;
        As[aCol + 2][aRow] = av.z;
        As[aCol + 3][aRow] = av.w;

        float4 bv = make_float4(0.f, 0.f, 0.f, 0.f);
        if (colBase + bCol < M)
            bv = *(const float4*)(W + (size_t)(k0 + bRow) * M + colBase + bCol);
        *(float4*)&Bs[bRow][bCol] = bv;
        __syncthreads();

        #pragma unroll
        for (int kk = 0; kk < 16; kk++) {
            float4 a4 = *(const float4*)&As[kk][ty << 2];
            float4 b4 = *(const float4*)&Bs[kk][tx << 2];
            float ar[4] = {a4.x, a4.y, a4.z, a4.w};
            float br[4] = {b4.x, b4.y, b4.z, b4.w};
            #pragma unroll
            for (int i = 0; i < 4; i++)
                #pragma unroll
                for (int j = 0; j < 4; j++)
                    acc[i][j] += ar[i] * br[j];
        }
        __syncthreads();
    }

    #pragma unroll
    for (int i = 0; i < 4; i++) {
        int r = rowBase + (ty << 2) + i;
        if (r >= Nrows) continue;
        #pragma unroll
        for (int j = 0; j < 4; j++) {
            int c = colBase + (tx << 2) + j;
            if (c < M)
                C[(size_t)r * M + c] = acc[i][j] + bias[c];
        }
    }
}

// ---------------------------------------------------------------------------
// wk[n,d,h] = sum_u We[d, h*32+u] * k[n, h*32+u]
// 256 threads: thread t owns (d = t>>2, h = t&3). We column held in registers
// (rotated by lane to make shared-mem k reads bank-conflict-free).
// ---------------------------------------------------------------------------
__global__ void wk_kernel(const float* __restrict__ We, int N) {
    __shared__ float sK[128];
    int t = threadIdx.x;
    int d = t >> 2, h = t & 3;

    float we_r[32];
    #pragma unroll
    for (int u = 0; u < 32; u++) {
        int uu = (u + t) & 31;
        we_r[u] = We[d * 128 + h * 32 + uu];
    }

    for (int n = blockIdx.x; n < N; n += gridDim.x) {
        __syncthreads();
        if (t < 128) sK[t] = g_k[(size_t)n * 128 + t];
        __syncthreads();
        float acc = 0.f;
        #pragma unroll
        for (int u = 0; u < 32; u++) {
            int uu = (u + t) & 31;
            acc += we_r[u] * sK[h * 32 + uu];
        }
        g_wk[(size_t)n * 256 + t] = acc;
    }
}

// bk[n,h] = sum_u be[h*32+u] * k[n, h*32+u]
__global__ void bk_kernel(const float* __restrict__ be, int N) {
    int t = blockIdx.x * blockDim.x + threadIdx.x;
    if (t >= N * 4) return;
    int n = t >> 2, h = t & 3;
    const float* kr = g_k + (size_t)n * 128 + h * 32;
    const float* br = be + h * 32;
    float acc = 0.f;
    #pragma unroll
    for (int u = 0; u < 32; u++) acc += br[u] * kr[u];
    g_bk[t] = acc;
}

// row_ptr[n] = lower_bound(src, n); src sorted ascending
__global__ void rowptr_kernel(const int* __restrict__ src, int N, int E) {
    int n = blockIdx.x * blockDim.x + threadIdx.x;
    if (n > N) return;
    if (n == N) { g_rowptr[N] = E; return; }
    int lo = 0, hi = E;
    while (lo < hi) {
        int mid = (lo + hi) >> 1;
        if (src[mid] < n) lo = mid + 1; else hi = mid;
    }
    g_rowptr[n] = lo;
}

// ---------------------------------------------------------------------------
// scores[e,h] = q[src]·k[dst] (per head) + ef[e]·wk[dst,:,h] + bk[dst,h]
// warp per edge
// ---------------------------------------------------------------------------
__global__ void scores_kernel(const int* __restrict__ src,
                              const int* __restrict__ dst,
                              const float* __restrict__ ef, int E) {
    int w = (int)((blockIdx.x * blockDim.x + threadIdx.x) >> 5);
    int lane = threadIdx.x & 31;
    if (w >= E) return;

    int s = src[w], d = dst[w];
    const float* qr = g_q + (size_t)s * 128;
    const float* kr = g_k + (size_t)d * 128;

    float p0 = qr[lane]      * kr[lane];
    float p1 = qr[32 + lane] * kr[32 + lane];
    float p2 = qr[64 + lane] * kr[64 + lane];
    float p3 = qr[96 + lane] * kr[96 + lane];

    const float* efr = ef + (size_t)w * 64;
    const float* wkr = g_wk + (size_t)d * 256;
    float e0 = efr[lane], e1 = efr[32 + lane];
    float4 w0 = *(const float4*)(wkr + lane * 4);
    float4 w1 = *(const float4*)(wkr + 128 + lane * 4);
    p0 += e0 * w0.x + e1 * w1.x;
    p1 += e0 * w0.y + e1 * w1.y;
    p2 += e0 * w0.z + e1 * w1.z;
    p3 += e0 * w0.w + e1 * w1.w;

    #pragma unroll
    for (int off = 16; off; off >>= 1) {
        p0 += __shfl_xor_sync(0xffffffffu, p0, off);
        p1 += __shfl_xor_sync(0xffffffffu, p1, off);
        p2 += __shfl_xor_sync(0xffffffffu, p2, off);
        p3 += __shfl_xor_sync(0xffffffffu, p3, off);
    }

    if (lane < 4) {
        float r = (lane == 0) ? p0 : (lane == 1) ? p1 : (lane == 2) ? p2 : p3;
        g_scores[(size_t)w * 4 + lane] = r + g_bk[(size_t)d * 4 + lane];
    }
}

// ---------------------------------------------------------------------------
// Fused segmented softmax + weighted aggregation. Warp per node (src sorted ->
// contiguous edge segment). No atomics.
// ---------------------------------------------------------------------------
__global__ void agg_kernel(const int* __restrict__ dst, int N) {
    int w = (int)((blockIdx.x * blockDim.x + threadIdx.x) >> 5);
    int lane = threadIdx.x & 31;
    if (w >= N) return;

    int s0 = g_rowptr[w], s1 = g_rowptr[w + 1];

    float m0 = -INFINITY, m1 = -INFINITY, m2 = -INFINITY, m3 = -INFINITY;
    for (int e = s0 + lane; e < s1; e += 32) {
        float4 sc = *(const float4*)(g_scores + (size_t)e * 4);
        m0 = fmaxf(m0, sc.x); m1 = fmaxf(m1, sc.y);
        m2 = fmaxf(m2, sc.z); m3 = fmaxf(m3, sc.w);
    }
    #pragma unroll
    for (int off = 16; off; off >>= 1) {
        m0 = fmaxf(m0, __shfl_xor_sync(0xffffffffu, m0, off));
        m1 = fmaxf(m1, __shfl_xor_sync(0xffffffffu, m1, off));
        m2 = fmaxf(m2, __shfl_xor_sync(0xffffffffu, m2, off));
        m3 = fmaxf(m3, __shfl_xor_sync(0xffffffffu, m3, off));
    }

    float z0 = 0.f, z1 = 0.f, z2 = 0.f, z3 = 0.f;
    for (int e = s0 + lane; e < s1; e += 32) {
        float4 sc = *(const float4*)(g_scores + (size_t)e * 4);
        sc.x = expf(sc.x - m0); sc.y = expf(sc.y - m1);
        sc.z = expf(sc.z - m2); sc.w = expf(sc.w - m3);
        *(float4*)(g_scores + (size_t)e * 4) = sc;
        z0 += sc.x; z1 += sc.y; z2 += sc.z; z3 += sc.w;
    }
    #pragma unroll
    for (int off = 16; off; off >>= 1) {
        z0 += __shfl_xor_sync(0xffffffffu, z0, off);
        z1 += __shfl_xor_sync(0xffffffffu, z1, off);
        z2 += __shfl_xor_sync(0xffffffffu, z2, off);
        z3 += __shfl_xor_sync(0xffffffffu, z3, off);
    }

    float a0 = 0.f, a1 = 0.f, a2 = 0.f, a3 = 0.f;
    for (int e = s0; e < s1; e++) {
        float4 ww = *(const float4*)(g_scores + (size_t)e * 4);
        int dd = dst[e];
        const float* vr = g_v + (size_t)dd * 128;
        a0 += ww.x * vr[lane];
        a1 += ww.y * vr[32 + lane];
        a2 += ww.z * vr[64 + lane];
        a3 += ww.w * vr[96 + lane];
    }

    float i0 = (z0 > 0.f) ? 1.f / z0 : 0.f;
    float i1 = (z1 > 0.f) ? 1.f / z1 : 0.f;
    float i2 = (z2 > 0.f) ? 1.f / z2 : 0.f;
    float i3 = (z3 > 0.f) ? 1.f / z3 : 0.f;

    float* ar = g_att + (size_t)w * 128;
    ar[lane]      = a0 * i0;
    ar[32 + lane] = a1 * i1;
    ar[64 + lane] = a2 * i2;
    ar[96 + lane] = a3 * i3;
}

// ---------------------------------------------------------------------------
// out = relu(att @ Wo + bo). Warp per row, Wo in shared, row in registers,
// broadcast via shfl.
// ---------------------------------------------------------------------------
__global__ void out_kernel(const float* __restrict__ Wo,
                           const float* __restrict__ bo,
                           float* __restrict__ out, int N) {
    __shared__ float sWo[128 * 32];
    __shared__ float sBo[32];
    int t = threadIdx.x;
    for (int i = t; i < 128 * 32; i += 256) sWo[i] = Wo[i];
    if (t < 32) sBo[t] = bo[t];
    __syncthreads();

    int lane = t & 31;
    int gw = blockIdx.x * 8 + (t >> 5);
    int stride = gridDim.x * 8;
    for (int row = gw; row < N; row += stride) {
        const float* ar = g_att + (size_t)row * 128;
        float a0 = ar[lane], a1 = ar[32 + lane], a2 = ar[64 + lane], a3 = ar[96 + lane];
        float acc = 0.f;
        #pragma unroll
        for (int k = 0; k < 128; k++) {
            float ak;
            if (k < 32)       ak = __shfl_sync(0xffffffffu, a0, k);
            else if (k < 64)  ak = __shfl_sync(0xffffffffu, a1, k - 32);
            else if (k < 96)  ak = __shfl_sync(0xffffffffu, a2, k - 64);
            else              ak = __shfl_sync(0xffffffffu, a3, k - 96);
            acc += ak * sWo[k * 32 + lane];
        }
        acc += sBo[lane];
        out[(size_t)row * 32 + lane] = fmaxf(acc, 0.f);
    }
}

// ---------------------------------------------------------------------------
extern "C" void kernel_launch(void* const* d_in, const int* in_sizes, int n_in,
                              void* d_out, int out_size) {
    const float* inputs = (const float*)d_in[0];
    const int*   eidx   = (const int*)d_in[1];
    const float* ef     = (const float*)d_in[2];
    const float* Wq     = (const float*)d_in[3];
    const float* bq     = (const float*)d_in[4];
    const float* Wk     = (const float*)d_in[5];
    const float* bkb    = (const float*)d_in[6];
    const float* Wv     = (const float*)d_in[7];
    const float* bv     = (const float*)d_in[8];
    const float* We     = (const float*)d_in[9];
    const float* be     = (const float*)d_in[10];
    const float* Wo     = (const float*)d_in[11];
    const float* bo     = (const float*)d_in[12];

    int N = in_sizes[0] / 128;
    int E = in_sizes[1] / 2;
    const int* src = eidx;
    const int* dst = eidx + E;

    float *qp, *kp, *vp;
    cudaGetSymbolAddress((void**)&qp, g_q);
    cudaGetSymbolAddress((void**)&kp, g_k);
    cudaGetSymbolAddress((void**)&vp, g_v);

    dim3 gg(2, (N + 63) / 64);
    sgemm_bias_kernel<<<gg, 256>>>(inputs, Wq, bq, qp, N, 128, 128);
    sgemm_bias_kernel<<<gg, 256>>>(inputs, Wk, bkb, kp, N, 128, 128);
    sgemm_bias_kernel<<<gg, 256>>>(inputs, Wv, bv, vp, N, 128, 128);

    wk_kernel<<<2048, 256>>>(We, N);
    bk_kernel<<<(N * 4 + 255) / 256, 256>>>(be, N);
    rowptr_kernel<<<(N + 1 + 255) / 256, 256>>>(src, N, E);

    scores_kernel<<<(E + 7) / 8, 256>>>(src, dst, ef, E);
    agg_kernel<<<(N + 7) / 8, 256>>>(dst, N);

    out_kernel<<<1024, 256>>>(Wo, bo, (float*)d_out, N);
}

// round 9
// speedup vs baseline: 1.0951x; 1.0951x over previous
#include <cuda_runtime.h>
#include <math.h>

#define MAXN 50000
#define MAXE 800000

__device__ float g_q[MAXN * 128];
__device__ float g_k[MAXN * 128];
__device__ float g_v[MAXN * 128];
__device__ float g_wk[(size_t)MAXN * 256];   // [n][d(64)][h(4)]
__device__ float g_bk[MAXN * 4];
__device__ float g_scores[(size_t)MAXE * 4]; // [e][h], reused for exp values
__device__ int   g_rowptr[MAXN + 1];
__device__ float g_att[MAXN * 128];
__device__ float g_W[128 * 384];             // packed Wq|Wk|Wv
__device__ float g_b[384];                   // packed bq|bk|bv

// ---------------------------------------------------------------------------
// Pack Wq,Wk,Wv -> g_W [128][384], biases -> g_b[384]
// ---------------------------------------------------------------------------
__global__ void pack_kernel(const float* __restrict__ Wq, const float* __restrict__ bq,
                            const float* __restrict__ Wk, const float* __restrict__ bk,
                            const float* __restrict__ Wv, const float* __restrict__ bv) {
    int i = blockIdx.x * blockDim.x + threadIdx.x;
    if (i < 128 * 384) {
        int r = i / 384, c = i % 384;
        float v;
        if (c < 128)      v = Wq[r * 128 + c];
        else if (c < 256) v = Wk[r * 128 + (c - 128)];
        else              v = Wv[r * 128 + (c - 256)];
        g_W[i] = v;
    }
    if (i < 384) {
        float v;
        if (i < 128)      v = bq[i];
        else if (i < 256) v = bk[i - 128];
        else              v = bv[i - 256];
        g_b[i] = v;
    }
}

// ---------------------------------------------------------------------------
// Fused QKV GEMM: C[N,384] = A[N,128] @ g_W[128,384] + g_b, split into
// g_q/g_k/g_v by 128-column block. BM=128 BN=128 BK=8, 256 thr, 8x8 microtile.
// ---------------------------------------------------------------------------
__global__ void qkv_gemm_kernel(const float* __restrict__ A, int Nrows) {
    __shared__ float As[8][132];   // transposed, padded
    __shared__ float Bs[8][128];

    int t = threadIdx.x;
    int rowBase = blockIdx.y * 128;
    int colBase = blockIdx.x * 128;

    int ty = t >> 4, tx = t & 15;      // 16x16 thread grid

    int aRow = t >> 1;                 // 0..127
    int aK   = (t & 1) * 4;            // 0 or 4
    int bK   = t >> 5;                 // 0..7
    int bCol = (t & 31) * 4;           // 0..124

    float acc[8][8] = {};

    for (int k0 = 0; k0 < 128; k0 += 8) {
        float4 av = make_float4(0.f, 0.f, 0.f, 0.f);
        int gr = rowBase + aRow;
        if (gr < Nrows)
            av = *(const float4*)(A + (size_t)gr * 128 + k0 + aK);
        As[aK + 0][aRow] = av.x;
        As[aK + 1][aRow] = av.y;
        As[aK + 2][aRow] = av.z;
        As[aK + 3][aRow] = av.w;

        float4 bv = *(const float4*)(g_W + (size_t)(k0 + bK) * 384 + colBase + bCol);
        *(float4*)&Bs[bK][bCol] = bv;
        __syncthreads();

        #pragma unroll
        for (int kk = 0; kk < 8; kk++) {
            float ar[8], br[8];
            *(float4*)&ar[0] = *(const float4*)&As[kk][ty * 8];
            *(float4*)&ar[4] = *(const float4*)&As[kk][ty * 8 + 4];
            *(float4*)&br[0] = *(const float4*)&Bs[kk][tx * 8];
            *(float4*)&br[4] = *(const float4*)&Bs[kk][tx * 8 + 4];
            #pragma unroll
            for (int i = 0; i < 8; i++)
                #pragma unroll
                for (int j = 0; j < 8; j++)
                    acc[i][j] += ar[i] * br[j];
        }
        __syncthreads();
    }

    float* dstbuf = (colBase == 0) ? g_q : (colBase == 128) ? g_k : g_v;

    #pragma unroll
    for (int i = 0; i < 8; i++) {
        int r = rowBase + ty * 8 + i;
        if (r >= Nrows) continue;
        #pragma unroll
        for (int j = 0; j < 8; j += 4) {
            int c = tx * 8 + j;
            float4 o;
            o.x = acc[i][j + 0] + g_b[colBase + c + 0];
            o.y = acc[i][j + 1] + g_b[colBase + c + 1];
            o.z = acc[i][j + 2] + g_b[colBase + c + 2];
            o.w = acc[i][j + 3] + g_b[colBase + c + 3];
            *(float4*)(dstbuf + (size_t)r * 128 + c) = o;
        }
    }
}

// ---------------------------------------------------------------------------
// wk[n,d,h] = sum_u We[d, h*32+u] * k[n, h*32+u]
// Also (fused) bk[n,h] = sum_u be[h*32+u] * k[n, h*32+u], computed by the
// d0==0 threads in a short second pass while sK is still live.
// 16 nodes per block, 2 syncs. Thread t owns h=t&3, d0=(t>>2)&31 and d0+32,
// node subgroup g=t>>7 (8 nodes each). Rotated index -> conflict-free LDS,
// each LDS feeds 2 FFMAs.
// ---------------------------------------------------------------------------
__global__ void wk_kernel(const float* __restrict__ We,
                          const float* __restrict__ be, int N) {
    __shared__ float sK[16 * 128];
    int t = threadIdx.x;
    int h = t & 3, d0 = (t >> 2) & 31;
    int g = t >> 7;

    float wr0[32], wr1[32];
    #pragma unroll
    for (int u = 0; u < 32; u++) {
        int uu = (u + t) & 31;
        wr0[u] = We[d0 * 128 + h * 32 + uu];
        wr1[u] = We[(d0 + 32) * 128 + h * 32 + uu];
    }

    int n0 = blockIdx.x * 16;
    // load 16 k rows (2048 floats) with float4s: 256 threads x 2
    #pragma unroll
    for (int i = 0; i < 2; i++) {
        int f4 = t + i * 256;                 // 0..511
        size_t gidx = (size_t)n0 * 128 + (size_t)f4 * 4;
        float4 kv = make_float4(0.f, 0.f, 0.f, 0.f);
        if (gidx < (size_t)N * 128)
            kv = *(const float4*)(g_k + gidx);
        *(float4*)&sK[f4 * 4] = kv;
    }
    __syncthreads();

    #pragma unroll
    for (int nb = 0; nb < 8; nb++) {
        int nl = g * 8 + nb;
        int n = n0 + nl;
        const float* kr = &sK[nl * 128 + h * 32];
        float a0 = 0.f, a1 = 0.f;
        #pragma unroll
        for (int u = 0; u < 32; u++) {
            float kv = kr[(u + t) & 31];
            a0 += wr0[u] * kv;
            a1 += wr1[u] * kv;
        }
        if (n < N) {
            g_wk[(size_t)n * 256 + (t & 127)]       = a0;
            g_wk[(size_t)n * 256 + 128 + (t & 127)] = a1;
        }
    }

    // fused bk: 8 threads (d0==0: one per (h, g)) cover all 16 nodes x 4 heads
    if (d0 == 0) {
        for (int nb = 0; nb < 8; nb++) {
            int nl = g * 8 + nb;
            int n = n0 + nl;
            if (n >= N) break;
            const float* kr = &sK[nl * 128 + h * 32];
            float b = 0.f;
            #pragma unroll
            for (int u = 0; u < 32; u++)
                b += __ldg(be + h * 32 + u) * kr[u];
            g_bk[(size_t)n * 4 + h] = b;
        }
    }
}

// row_ptr[n] = lower_bound(src, n); src sorted ascending
__global__ void rowptr_kernel(const int* __restrict__ src, int N, int E) {
    int n = blockIdx.x * blockDim.x + threadIdx.x;
    if (n > N) return;
    if (n == N) { g_rowptr[N] = E; return; }
    int lo = 0, hi = E;
    while (lo < hi) {
        int mid = (lo + hi) >> 1;
        if (src[mid] < n) lo = mid + 1; else hi = mid;
    }
    g_rowptr[n] = lo;
}

// ---------------------------------------------------------------------------
// scores[e,h] = q[src]·k[dst] (per head) + ef[e]·wk[dst,:,h] + bk[dst,h]
// warp per edge
// ---------------------------------------------------------------------------
__global__ void scores_kernel(const int* __restrict__ src,
                              const int* __restrict__ dst,
                              const float* __restrict__ ef, int E) {
    int w = (int)((blockIdx.x * blockDim.x + threadIdx.x) >> 5);
    int lane = threadIdx.x & 31;
    if (w >= E) return;

    int s = src[w], d = dst[w];
    const float* qr = g_q + (size_t)s * 128;
    const float* kr = g_k + (size_t)d * 128;

    float p0 = __ldg(qr + lane)      * __ldg(kr + lane);
    float p1 = __ldg(qr + 32 + lane) * __ldg(kr + 32 + lane);
    float p2 = __ldg(qr + 64 + lane) * __ldg(kr + 64 + lane);
    float p3 = __ldg(qr + 96 + lane) * __ldg(kr + 96 + lane);

    const float* efr = ef + (size_t)w * 64;
    const float* wkr = g_wk + (size_t)d * 256;
    float e0 = __ldg(efr + lane), e1 = __ldg(efr + 32 + lane);
    float4 w0 = __ldg((const float4*)(wkr + lane * 4));
    float4 w1 = __ldg((const float4*)(wkr + 128 + lane * 4));
    p0 += e0 * w0.x + e1 * w1.x;
    p1 += e0 * w0.y + e1 * w1.y;
    p2 += e0 * w0.z + e1 * w1.z;
    p3 += e0 * w0.w + e1 * w1.w;

    #pragma unroll
    for (int off = 16; off; off >>= 1) {
        p0 += __shfl_xor_sync(0xffffffffu, p0, off);
        p1 += __shfl_xor_sync(0xffffffffu, p1, off);
        p2 += __shfl_xor_sync(0xffffffffu, p2, off);
        p3 += __shfl_xor_sync(0xffffffffu, p3, off);
    }

    if (lane < 4) {
        float r = (lane == 0) ? p0 : (lane == 1) ? p1 : (lane == 2) ? p2 : p3;
        g_scores[(size_t)w * 4 + lane] = r + g_bk[(size_t)d * 4 + lane];
    }
}

// ---------------------------------------------------------------------------
// Fused segmented softmax + weighted aggregation. Warp per node.
// ---------------------------------------------------------------------------
__global__ void agg_kernel(const int* __restrict__ dst, int N) {
    int w = (int)((blockIdx.x * blockDim.x + threadIdx.x) >> 5);
    int lane = threadIdx.x & 31;
    if (w >= N) return;

    int s0 = g_rowptr[w], s1 = g_rowptr[w + 1];

    float m0 = -INFINITY, m1 = -INFINITY, m2 = -INFINITY, m3 = -INFINITY;
    for (int e = s0 + lane; e < s1; e += 32) {
        float4 sc = *(const float4*)(g_scores + (size_t)e * 4);
        m0 = fmaxf(m0, sc.x); m1 = fmaxf(m1, sc.y);
        m2 = fmaxf(m2, sc.z); m3 = fmaxf(m3, sc.w);
    }
    #pragma unroll
    for (int off = 16; off; off >>= 1) {
        m0 = fmaxf(m0, __shfl_xor_sync(0xffffffffu, m0, off));
        m1 = fmaxf(m1, __shfl_xor_sync(0xffffffffu, m1, off));
        m2 = fmaxf(m2, __shfl_xor_sync(0xffffffffu, m2, off));
        m3 = fmaxf(m3, __shfl_xor_sync(0xffffffffu, m3, off));
    }

    float z0 = 0.f, z1 = 0.f, z2 = 0.f, z3 = 0.f;
    for (int e = s0 + lane; e < s1; e += 32) {
        float4 sc = *(const float4*)(g_scores + (size_t)e * 4);
        sc.x = expf(sc.x - m0); sc.y = expf(sc.y - m1);
        sc.z = expf(sc.z - m2); sc.w = expf(sc.w - m3);
        *(float4*)(g_scores + (size_t)e * 4) = sc;
        z0 += sc.x; z1 += sc.y; z2 += sc.z; z3 += sc.w;
    }
    #pragma unroll
    for (int off = 16; off; off >>= 1) {
        z0 += __shfl_xor_sync(0xffffffffu, z0, off);
        z1 += __shfl_xor_sync(0xffffffffu, z1, off);
        z2 += __shfl_xor_sync(0xffffffffu, z2, off);
        z3 += __shfl_xor_sync(0xffffffffu, z3, off);
    }

    float a0 = 0.f, a1 = 0.f, a2 = 0.f, a3 = 0.f;
    #pragma unroll 2
    for (int e = s0; e < s1; e++) {
        float4 ww = *(const float4*)(g_scores + (size_t)e * 4);
        int dd = dst[e];
        const float* vr = g_v + (size_t)dd * 128;
        a0 += ww.x * __ldg(vr + lane);
        a1 += ww.y * __ldg(vr + 32 + lane);
        a2 += ww.z * __ldg(vr + 64 + lane);
        a3 += ww.w * __ldg(vr + 96 + lane);
    }

    float i0 = (z0 > 0.f) ? 1.f / z0 : 0.f;
    float i1 = (z1 > 0.f) ? 1.f / z1 : 0.f;
    float i2 = (z2 > 0.f) ? 1.f / z2 : 0.f;
    float i3 = (z3 > 0.f) ? 1.f / z3 : 0.f;

    float* ar = g_att + (size_t)w * 128;
    ar[lane]      = a0 * i0;
    ar[32 + lane] = a1 * i1;
    ar[64 + lane] = a2 * i2;
    ar[96 + lane] = a3 * i3;
}

// ---------------------------------------------------------------------------
// out = relu(att @ Wo + bo). Warp per row, Wo in shared, shfl broadcast.
// ---------------------------------------------------------------------------
__global__ void out_kernel(const float* __restrict__ Wo,
                           const float* __restrict__ bo,
                           float* __restrict__ out, int N) {
    __shared__ float sWo[128 * 32];
    __shared__ float sBo[32];
    int t = threadIdx.x;
    for (int i = t; i < 128 * 32; i += 256) sWo[i] = Wo[i];
    if (t < 32) sBo[t] = bo[t];
    __syncthreads();

    int lane = t & 31;
    int gw = blockIdx.x * 8 + (t >> 5);
    int stride = gridDim.x * 8;
    for (int row = gw; row < N; row += stride) {
        const float* ar = g_att + (size_t)row * 128;
        float a0 = ar[lane], a1 = ar[32 + lane], a2 = ar[64 + lane], a3 = ar[96 + lane];
        float acc = 0.f;
        #pragma unroll
        for (int k = 0; k < 128; k++) {
            float ak;
            if (k < 32)       ak = __shfl_sync(0xffffffffu, a0, k);
            else if (k < 64)  ak = __shfl_sync(0xffffffffu, a1, k - 32);
            else if (k < 96)  ak = __shfl_sync(0xffffffffu, a2, k - 64);
            else              ak = __shfl_sync(0xffffffffu, a3, k - 96);
            acc += ak * sWo[k * 32 + lane];
        }
        acc += sBo[lane];
        out[(size_t)row * 32 + lane] = fmaxf(acc, 0.f);
    }
}

// ---------------------------------------------------------------------------
extern "C" void kernel_launch(void* const* d_in, const int* in_sizes, int n_in,
                              void* d_out, int out_size) {
    const float* inputs = (const float*)d_in[0];
    const int*   eidx   = (const int*)d_in[1];
    const float* ef     = (const float*)d_in[2];
    const float* Wq     = (const float*)d_in[3];
    const float* bq     = (const float*)d_in[4];
    const float* Wk     = (const float*)d_in[5];
    const float* bkb    = (const float*)d_in[6];
    const float* Wv     = (const float*)d_in[7];
    const float* bv     = (const float*)d_in[8];
    const float* We     = (const float*)d_in[9];
    const float* be     = (const float*)d_in[10];
    const float* Wo     = (const float*)d_in[11];
    const float* bo     = (const float*)d_in[12];

    int N = in_sizes[0] / 128;
    int E = in_sizes[1] / 2;
    const int* src = eidx;
    const int* dst = eidx + E;

    pack_kernel<<<(128 * 384 + 255) / 256, 256>>>(Wq, bq, Wk, bkb, Wv, bv);

    dim3 gg(3, (N + 127) / 128);
    qkv_gemm_kernel<<<gg, 256>>>(inputs, N);

    wk_kernel<<<(N + 15) / 16, 256>>>(We, be, N);
    rowptr_kernel<<<(N + 1 + 255) / 256, 256>>>(src, N, E);

    scores_kernel<<<(E + 7) / 8, 256>>>(src, dst, ef, E);
    agg_kernel<<<(N + 7) / 8, 256>>>(dst, N);

    out_kernel<<<1024, 256>>>(Wo, bo, (float*)d_out, N);
}